// round 3
// baseline (speedup 1.0000x reference)
#include <cuda_runtime.h>
#include <cuda_bf16.h>
#include <cstdint>
#include <math.h>

#define DIM     2048
#define NEXP    64
#define NTOK    16384
#define BM      64            // tokens per CTA (4 warps x 16 rows)
#define KC      128           // K elems per smem chunk
#define NCHUNK  (DIM / KC)    // 16
#define BROWB   272           // bytes per B smem row (128+8 bf16, conflict-free for ldmatrix)
#define GRP_B   4352          // 16 rows * 272B (one n16 ldmatrix group)
#define BLK_B   17408         // 64 rows * 272B (one split, one stage)
#define OFF_B(s, sp) (((s) * 2 + (sp)) * BLK_B)
#define OFF_BIAS 69632
#define SMEM_SZ  69888
#define TAU 1e-4f

// precomputed W^T bf16 hi/lo: [expert][k]
__device__ unsigned short g_WtHi[NEXP * DIM];
__device__ unsigned short g_WtLo[NEXP * DIM];
__device__ int g_count;
__device__ int g_flags[NTOK];

// ---------- helpers ----------
__device__ __forceinline__ uint32_t smem_u32(const void* p) {
    uint32_t a;
    asm("{ .reg .u64 t; cvta.to.shared.u64 t, %1; cvt.u32.u64 %0, t; }" : "=r"(a) : "l"(p));
    return a;
}
// pack (lo_elem, hi_elem) -> bf16x2 with lo_elem in low 16 bits
#define CVT2(r, loe, hie) asm("cvt.rn.bf16x2.f32 %0, %1, %2;" : "=r"(r) : "f"(hie), "f"(loe))

#define LDSM4(r0, r1, r2, r3, a)                                               \
    asm volatile("ldmatrix.sync.aligned.m8n8.x4.shared.b16 {%0,%1,%2,%3}, [%4];" \
                 : "=r"(r0), "=r"(r1), "=r"(r2), "=r"(r3) : "r"(a))

#define MMA(c, a0, a1, a2, a3, b0, b1)                                         \
    asm volatile("mma.sync.aligned.m16n8k16.row.col.f32.bf16.bf16.f32 "        \
                 "{%0,%1,%2,%3},{%4,%5,%6,%7},{%8,%9},{%0,%1,%2,%3};"          \
                 : "+f"((c)[0]), "+f"((c)[1]), "+f"((c)[2]), "+f"((c)[3])      \
                 : "r"(a0), "r"(a1), "r"(a2), "r"(a3), "r"(b0), "r"(b1))

__device__ __forceinline__ void cp16(uint32_t dst, const void* src) {
    asm volatile("cp.async.ca.shared.global [%0], [%1], 16;" :: "r"(dst), "l"(src));
}
#define CP_COMMIT() asm volatile("cp.async.commit_group;" ::: "memory")
#define CP_WAIT(n)  asm volatile("cp.async.wait_group %0;" :: "n"(n) : "memory")

// ---------- prep: W [k][e] f32 -> Wt hi/lo bf16 [e][k], coalesced via smem ----------
__global__ void prep_w_kernel(const float* __restrict__ W) {
    __shared__ float tile[64][65];
    const int t = threadIdx.x;
    const int k0 = blockIdx.x * 64;
    if (blockIdx.x == 0 && t == 0) g_count = 0;
    {
        int kr = t >> 2, ec = (t & 3) * 16;
        #pragma unroll
        for (int i = 0; i < 4; ++i) {
            float4 v = *(const float4*)&W[(size_t)(k0 + kr) * NEXP + ec + i * 4];
            tile[kr][ec + i * 4 + 0] = v.x;
            tile[kr][ec + i * 4 + 1] = v.y;
            tile[kr][ec + i * 4 + 2] = v.z;
            tile[kr][ec + i * 4 + 3] = v.w;
        }
    }
    __syncthreads();
    {
        int e = t >> 2, part = t & 3;
        #pragma unroll
        for (int i = 0; i < 16; ++i) {
            int kl = part * 16 + i;
            float w = tile[kl][e];
            __nv_bfloat16 hb = __float2bfloat16(w);
            float lo = w - __bfloat162float(hb);
            size_t idx = (size_t)e * DIM + k0 + kl;
            g_WtHi[idx] = __bfloat16_as_ushort(hb);
            g_WtLo[idx] = __bfloat16_as_ushort(__float2bfloat16(lo));
        }
    }
}

// ---------- main: HMMA router ----------
__global__ __launch_bounds__(128)
void router_mma_kernel(const float* __restrict__ x,
                       const float* __restrict__ b,
                       float* __restrict__ out) {
    extern __shared__ char smem[];
    const uint32_t sb = smem_u32(smem);
    const int tid  = threadIdx.x;
    const int lane = tid & 31;
    const int wid  = tid >> 5;
    const int m0   = blockIdx.x * BM;

    float* biasArr = (float*)(smem + OFF_BIAS);
    if (tid < NEXP) biasArr[tid] = b[tid];

    // ---- B stage fill via cp.async (both splits), 16B granules ----
    auto stage_fill = [&](int c, int s) {
        int n = tid >> 1, half = tid & 1;
        const char* srcH = (const char*)(g_WtHi + (size_t)n * DIM + c * KC) + half * 128;
        const char* srcL = (const char*)(g_WtLo + (size_t)n * DIM + c * KC) + half * 128;
        uint32_t dH = sb + OFF_B(s, 0) + n * BROWB + half * 128;
        uint32_t dL = sb + OFF_B(s, 1) + n * BROWB + half * 128;
        #pragma unroll
        for (int i = 0; i < 8; ++i) {
            cp16(dH + i * 16, srcH + i * 16);
            cp16(dL + i * 16, srcL + i * 16);
        }
    };

    // ---- A pointers: warp owns rows [m0 + wid*16, +16) ----
    const int rowL = m0 + wid * 16 + (lane >> 2);
    const float* xp0 = x + (size_t)rowL * DIM + (lane & 3) * 2;
    const float* xp1 = xp0 + (size_t)8 * DIM;

    float2 f0, f1, f2, f3;
    auto ldA = [&](int k, float2& a, float2& c0, float2& c1, float2& c2) {
        a  = *(const float2*)(xp0 + k);
        c0 = *(const float2*)(xp1 + k);
        c1 = *(const float2*)(xp0 + k + 8);
        c2 = *(const float2*)(xp1 + k + 8);
    };

    float acc[8][4];
    #pragma unroll
    for (int nf = 0; nf < 8; ++nf)
        #pragma unroll
        for (int q = 0; q < 4; ++q) acc[nf][q] = 0.0f;

    // ldmatrix lane addressing within a n16 group
    const int lnN = ((lane >> 4) & 1) * 8 + (lane & 7);
    const int lnK = ((lane >> 3) & 1) * 8;
    const uint32_t lmOff = (uint32_t)(lnN * BROWB + lnK * 2);

    stage_fill(0, 0);
    CP_COMMIT();
    ldA(0, f0, f1, f2, f3);

    for (int c = 0; c < NCHUNK; ++c) {
        const int s = c & 1;
        __syncthreads();                    // all warps done reading stage s^1
        if (c + 1 < NCHUNK) {
            stage_fill(c + 1, s ^ 1);
            CP_COMMIT();
            CP_WAIT(1);
        } else {
            CP_WAIT(0);
        }
        __syncthreads();                    // chunk c visible to all

        const uint32_t bH_base = sb + OFF_B(s, 0) + lmOff;
        const uint32_t bL_base = sb + OFF_B(s, 1) + lmOff;

        #pragma unroll
        for (int j = 0; j < 8; ++j) {
            // prefetch next A k16
            int kn = c * KC + j * 16 + 16;
            if (kn >= DIM) kn = 0;
            float2 g0, g1, g2, g3;
            ldA(kn, g0, g1, g2, g3);

            // convert A frag: hi + residual-lo
            uint32_t aH0, aH1, aH2, aH3, aL0, aL1, aL2, aL3;
            CVT2(aH0, f0.x, f0.y);
            CVT2(aH1, f1.x, f1.y);
            CVT2(aH2, f2.x, f2.y);
            CVT2(aH3, f3.x, f3.y);
            float e0, e1;
            e0 = f0.x - __uint_as_float(aH0 << 16);
            e1 = f0.y - __uint_as_float(aH0 & 0xffff0000u);
            CVT2(aL0, e0, e1);
            e0 = f1.x - __uint_as_float(aH1 << 16);
            e1 = f1.y - __uint_as_float(aH1 & 0xffff0000u);
            CVT2(aL1, e0, e1);
            e0 = f2.x - __uint_as_float(aH2 << 16);
            e1 = f2.y - __uint_as_float(aH2 & 0xffff0000u);
            CVT2(aL2, e0, e1);
            e0 = f3.x - __uint_as_float(aH3 << 16);
            e1 = f3.y - __uint_as_float(aH3 & 0xffff0000u);
            CVT2(aL3, e0, e1);

            // B fragments via ldmatrix (4 n16 groups per split)
            uint32_t bH[16], bL[16];
            #pragma unroll
            for (int g = 0; g < 4; ++g) {
                LDSM4(bH[4 * g + 0], bH[4 * g + 1], bH[4 * g + 2], bH[4 * g + 3],
                      bH_base + g * GRP_B + j * 32);
                LDSM4(bL[4 * g + 0], bL[4 * g + 1], bL[4 * g + 2], bL[4 * g + 3],
                      bL_base + g * GRP_B + j * 32);
            }

            #pragma unroll
            for (int nf = 0; nf < 8; ++nf)
                MMA(acc[nf], aH0, aH1, aH2, aH3, bH[2 * nf], bH[2 * nf + 1]);
            #pragma unroll
            for (int nf = 0; nf < 8; ++nf)
                MMA(acc[nf], aH0, aH1, aH2, aH3, bL[2 * nf], bL[2 * nf + 1]);
            #pragma unroll
            for (int nf = 0; nf < 8; ++nf)
                MMA(acc[nf], aL0, aL1, aL2, aL3, bH[2 * nf], bH[2 * nf + 1]);

            f0 = g0; f1 = g1; f2 = g2; f3 = g3;
        }
    }

    // ---- epilogue: stash logits in smem (overlay on B), top-2 + softmax ----
    __syncthreads();
    float* ls = (float*)smem + wid * (16 * 68);
    {
        const int r = lane >> 2, cb = (lane & 3) * 2;
        #pragma unroll
        for (int nf = 0; nf < 8; ++nf) {
            ls[r * 68 + nf * 8 + cb]           = acc[nf][0];
            ls[r * 68 + nf * 8 + cb + 1]       = acc[nf][1];
            ls[(r + 8) * 68 + nf * 8 + cb]     = acc[nf][2];
            ls[(r + 8) * 68 + nf * 8 + cb + 1] = acc[nf][3];
        }
    }
    __syncwarp();

    if (lane < 16) {
        const float NEG = __int_as_float(0xff800000);
        float m1 = NEG, m2 = NEG, m3 = NEG;
        int i1 = 0, i2 = 0;
        #pragma unroll
        for (int e = 0; e < NEXP; ++e) {
            float v = ls[lane * 68 + e] + biasArr[e];
            if (v > m1)      { m3 = m2; m2 = m1; i2 = i1; m1 = v; i1 = e; }
            else if (v > m2) { m3 = m2; m2 = v; i2 = e; }
            else if (v > m3) { m3 = v; }
        }
        float ssum = 0.0f;
        #pragma unroll
        for (int e = 0; e < NEXP; ++e)
            ssum += expf(ls[lane * 68 + e] + biasArr[e] - m1);

        const int tok = m0 + wid * 16 + lane;
        out[(size_t)tok * 2 + 0] = (float)i1;
        out[(size_t)tok * 2 + 1] = (float)i2;
        out[(size_t)2 * NTOK + tok * 2 + 0] = 1.0f / ssum;
        out[(size_t)2 * NTOK + tok * 2 + 1] = expf(m2 - m1) / ssum;

        // flag ambiguous tokens for exact fp32 rescue
        if ((m1 - m2) < TAU || (m2 - m3) < TAU) {
            int ix = atomicAdd(&g_count, 1);
            if (ix < NTOK) g_flags[ix] = tok;
        }
    }
}

// ---------- rescue: exact fp32 recompute for flagged tokens ----------
__global__ void rescue_kernel(const float* __restrict__ x,
                              const float* __restrict__ W,
                              const float* __restrict__ b,
                              float* __restrict__ out) {
    __shared__ float lg[NEXP];
    int cnt = g_count;
    if (cnt > NTOK) cnt = NTOK;
    const int e = threadIdx.x >> 2, q = threadIdx.x & 3;

    for (int i = blockIdx.x; i < cnt; i += gridDim.x) {
        const int tok = g_flags[i];
        const float* xr = x + (size_t)tok * DIM;
        float s = 0.0f;
        const int k0 = q * (DIM / 4);
        for (int k = k0; k < k0 + DIM / 4; ++k)
            s = fmaf(xr[k], W[(size_t)k * NEXP + e], s);
        s += __shfl_xor_sync(0xffffffffu, s, 1);
        s += __shfl_xor_sync(0xffffffffu, s, 2);
        if (q == 0) lg[e] = s + b[e];
        __syncthreads();

        if (threadIdx.x == 0) {
            const float NEG = __int_as_float(0xff800000);
            float m1 = NEG, m2 = NEG;
            int i1 = 0, i2 = 0;
            for (int ee = 0; ee < NEXP; ++ee) {
                float v = lg[ee];
                if (v > m1)      { m2 = m1; i2 = i1; m1 = v; i1 = ee; }
                else if (v > m2) { m2 = v; i2 = ee; }
            }
            float ssum = 0.0f;
            for (int ee = 0; ee < NEXP; ++ee) ssum += expf(lg[ee] - m1);
            out[(size_t)tok * 2 + 0] = (float)i1;
            out[(size_t)tok * 2 + 1] = (float)i2;
            out[(size_t)2 * NTOK + tok * 2 + 0] = 1.0f / ssum;
            out[(size_t)2 * NTOK + tok * 2 + 1] = expf(m2 - m1) / ssum;
        }
        __syncthreads();
    }
}

extern "C" void kernel_launch(void* const* d_in, const int* in_sizes, int n_in,
                              void* d_out, int out_size) {
    const float* x = (const float*)d_in[0];
    const float* W = (const float*)d_in[1];
    const float* b = (const float*)d_in[2];
    float* out = (float*)d_out;

    cudaFuncSetAttribute(router_mma_kernel,
                         cudaFuncAttributeMaxDynamicSharedMemorySize, SMEM_SZ);

    prep_w_kernel<<<DIM / 64, 256>>>(W);
    router_mma_kernel<<<NTOK / BM, 128, SMEM_SZ>>>(x, b, out);
    rescue_kernel<<<64, 256>>>(x, W, b, out);
}

// round 4
// speedup vs baseline: 1.5432x; 1.5432x over previous
#include <cuda_runtime.h>
#include <cuda_bf16.h>
#include <cstdint>
#include <math.h>

#define DIM     2048
#define NEXP    64
#define NTOK    16384
#define BM      64            // tokens per CTA
#define KC      128           // K elems per smem chunk
#define NCHUNK  (DIM / KC)    // 16
#define BROWB   272           // bytes per B smem row (128 bf16 + 8 pad)
#define GRP_B   4352          // 16 rows * 272B (one n16 ldmatrix group)
#define BLK_B   17408         // 64 rows * 272B (one split, one stage)
#define OFF_B(s, sp) (((s) * 2 + (sp)) * BLK_B)
#define OFF_BIAS 69632
#define SMEM_SZ  69888
#define TAU 1e-4f

__device__ unsigned short g_WtHi[NEXP * DIM];
__device__ unsigned short g_WtLo[NEXP * DIM];
__device__ int g_count;
__device__ int g_flags[NTOK];

// ---------- helpers ----------
__device__ __forceinline__ uint32_t smem_u32(const void* p) {
    uint32_t a;
    asm("{ .reg .u64 t; cvta.to.shared.u64 t, %1; cvt.u32.u64 %0, t; }" : "=r"(a) : "l"(p));
    return a;
}
#define CVT2(r, loe, hie) asm("cvt.rn.bf16x2.f32 %0, %1, %2;" : "=r"(r) : "f"(hie), "f"(loe))

#define LDSM4(r0, r1, r2, r3, a)                                               \
    asm volatile("ldmatrix.sync.aligned.m8n8.x4.shared.b16 {%0,%1,%2,%3}, [%4];" \
                 : "=r"(r0), "=r"(r1), "=r"(r2), "=r"(r3) : "r"(a))

#define MMA(c, a0, a1, a2, a3, b0, b1)                                         \
    asm volatile("mma.sync.aligned.m16n8k16.row.col.f32.bf16.bf16.f32 "        \
                 "{%0,%1,%2,%3},{%4,%5,%6,%7},{%8,%9},{%0,%1,%2,%3};"          \
                 : "+f"((c)[0]), "+f"((c)[1]), "+f"((c)[2]), "+f"((c)[3])      \
                 : "r"(a0), "r"(a1), "r"(a2), "r"(a3), "r"(b0), "r"(b1))

__device__ __forceinline__ void cp16(uint32_t dst, const void* src) {
    asm volatile("cp.async.ca.shared.global [%0], [%1], 16;" :: "r"(dst), "l"(src));
}
#define CP_COMMIT() asm volatile("cp.async.commit_group;" ::: "memory")
#define CP_WAIT(n)  asm volatile("cp.async.wait_group %0;" :: "n"(n) : "memory")

// ---------- prep: W [k][e] f32 -> Wt hi/lo bf16 [e][k] ----------
__global__ __launch_bounds__(256)
void prep_w_kernel(const float* __restrict__ W) {
    __shared__ float tile[32][65];
    const int t = threadIdx.x;
    const int k0 = blockIdx.x * 32;
    if (blockIdx.x == 0 && t == 0) g_count = 0;
    {
        int kr = t >> 3, e8 = (t & 7) * 8;
        float4 v0 = *(const float4*)&W[(size_t)(k0 + kr) * NEXP + e8];
        float4 v1 = *(const float4*)&W[(size_t)(k0 + kr) * NEXP + e8 + 4];
        tile[kr][e8 + 0] = v0.x; tile[kr][e8 + 1] = v0.y;
        tile[kr][e8 + 2] = v0.z; tile[kr][e8 + 3] = v0.w;
        tile[kr][e8 + 4] = v1.x; tile[kr][e8 + 5] = v1.y;
        tile[kr][e8 + 6] = v1.z; tile[kr][e8 + 7] = v1.w;
    }
    __syncthreads();
    {
        int e = t >> 2, part = t & 3;
        unsigned short hbuf[8], lbuf[8];
        #pragma unroll
        for (int i = 0; i < 8; ++i) {
            float w = tile[part * 8 + i][e];
            __nv_bfloat16 hb = __float2bfloat16(w);
            float lo = w - __bfloat162float(hb);
            hbuf[i] = __bfloat16_as_ushort(hb);
            lbuf[i] = __bfloat16_as_ushort(__float2bfloat16(lo));
        }
        size_t idx = (size_t)e * DIM + k0 + part * 8;
        *(uint4*)&g_WtHi[idx] = *(uint4*)hbuf;
        *(uint4*)&g_WtLo[idx] = *(uint4*)lbuf;
    }
}

// ---------- main: HMMA router, 8 warps, expert-split ----------
__global__ __launch_bounds__(256, 2)
void router_mma_kernel(const float* __restrict__ x,
                       const float* __restrict__ b,
                       float* __restrict__ out) {
    extern __shared__ char smem[];
    const uint32_t sb = smem_u32(smem);
    const int tid  = threadIdx.x;
    const int lane = tid & 31;
    const int wid  = tid >> 5;
    const int wq   = wid & 3;    // row group (16 rows)
    const int eh   = wid >> 2;   // expert half (32 experts)
    const int m0   = blockIdx.x * BM;

    float* biasArr = (float*)(smem + OFF_BIAS);
    if (tid < NEXP) biasArr[tid] = b[tid];

    // B stage fill via cp.async: 256 threads, each 4x16B per split
    auto stage_fill = [&](int c, int s) {
        int n = tid >> 2, q = tid & 3;
        const char* srcH = (const char*)(g_WtHi + (size_t)n * DIM + c * KC) + q * 64;
        const char* srcL = (const char*)(g_WtLo + (size_t)n * DIM + c * KC) + q * 64;
        uint32_t dH = sb + OFF_B(s, 0) + n * BROWB + q * 64;
        uint32_t dL = sb + OFF_B(s, 1) + n * BROWB + q * 64;
        #pragma unroll
        for (int i = 0; i < 4; ++i) {
            cp16(dH + i * 16, srcH + i * 16);
            cp16(dL + i * 16, srcL + i * 16);
        }
    };

    // A: warp owns rows [m0 + wq*16, +16)
    const int rowL = m0 + wq * 16 + (lane >> 2);
    const float* xp0 = x + (size_t)rowL * DIM + (lane & 3) * 2;
    const float* xp1 = xp0 + (size_t)8 * DIM;

    float2 f0, f1, f2, f3;
    auto ldA = [&](int k, float2& a, float2& c0, float2& c1, float2& c2) {
        a  = *(const float2*)(xp0 + k);
        c0 = *(const float2*)(xp1 + k);
        c1 = *(const float2*)(xp0 + k + 8);
        c2 = *(const float2*)(xp1 + k + 8);
    };

    float acc[4][4];
    #pragma unroll
    for (int nf = 0; nf < 4; ++nf)
        #pragma unroll
        for (int q = 0; q < 4; ++q) acc[nf][q] = 0.0f;

    const int lnN = ((lane >> 4) & 1) * 8 + (lane & 7);
    const int lnK = ((lane >> 3) & 1) * 8;
    const uint32_t lmOff = (uint32_t)(eh * 32 * BROWB + lnN * BROWB + lnK * 2);

    stage_fill(0, 0);
    CP_COMMIT();
    ldA(0, f0, f1, f2, f3);

    for (int c = 0; c < NCHUNK; ++c) {
        const int s = c & 1;
        __syncthreads();
        if (c + 1 < NCHUNK) {
            stage_fill(c + 1, s ^ 1);
            CP_COMMIT();
            CP_WAIT(1);
        } else {
            CP_WAIT(0);
        }
        __syncthreads();

        const uint32_t bH_base = sb + OFF_B(s, 0) + lmOff;
        const uint32_t bL_base = sb + OFF_B(s, 1) + lmOff;

        #pragma unroll
        for (int j = 0; j < 8; ++j) {
            int kn = c * KC + j * 16 + 16;
            if (kn >= DIM) kn = 0;
            float2 g0, g1, g2, g3;
            ldA(kn, g0, g1, g2, g3);

            // A fragments: bf16 hi + residual lo
            uint32_t aH0, aH1, aH2, aH3, aL0, aL1, aL2, aL3;
            CVT2(aH0, f0.x, f0.y);
            CVT2(aH1, f1.x, f1.y);
            CVT2(aH2, f2.x, f2.y);
            CVT2(aH3, f3.x, f3.y);
            float e0, e1;
            e0 = f0.x - __uint_as_float(aH0 << 16);
            e1 = f0.y - __uint_as_float(aH0 & 0xffff0000u);
            CVT2(aL0, e0, e1);
            e0 = f1.x - __uint_as_float(aH1 << 16);
            e1 = f1.y - __uint_as_float(aH1 & 0xffff0000u);
            CVT2(aL1, e0, e1);
            e0 = f2.x - __uint_as_float(aH2 << 16);
            e1 = f2.y - __uint_as_float(aH2 & 0xffff0000u);
            CVT2(aL2, e0, e1);
            e0 = f3.x - __uint_as_float(aH3 << 16);
            e1 = f3.y - __uint_as_float(aH3 & 0xffff0000u);
            CVT2(aL3, e0, e1);

            // two n16 groups; consume B fragments immediately (8 live B regs)
            #pragma unroll
            for (int g = 0; g < 2; ++g) {
                uint32_t h0, h1, h2, h3, l0, l1, l2, l3;
                LDSM4(h0, h1, h2, h3, bH_base + g * GRP_B + j * 32);
                LDSM4(l0, l1, l2, l3, bL_base + g * GRP_B + j * 32);
                MMA(acc[2 * g + 0], aH0, aH1, aH2, aH3, h0, h1);
                MMA(acc[2 * g + 1], aH0, aH1, aH2, aH3, h2, h3);
                MMA(acc[2 * g + 0], aH0, aH1, aH2, aH3, l0, l1);
                MMA(acc[2 * g + 1], aH0, aH1, aH2, aH3, l2, l3);
                MMA(acc[2 * g + 0], aL0, aL1, aL2, aL3, h0, h1);
                MMA(acc[2 * g + 1], aL0, aL1, aL2, aL3, h2, h3);
            }

            f0 = g0; f1 = g1; f2 = g2; f3 = g3;
        }
    }

    // ---- epilogue ----
    __syncthreads();
    float* ls = (float*)smem;   // 64 rows x 65 floats
    {
        const int r  = wq * 16 + (lane >> 2);
        const int cb = (lane & 3) * 2;
        #pragma unroll
        for (int nf = 0; nf < 4; ++nf) {
            const int e0 = eh * 32 + nf * 8 + cb;
            ls[r * 65 + e0]           = acc[nf][0];
            ls[r * 65 + e0 + 1]       = acc[nf][1];
            ls[(r + 8) * 65 + e0]     = acc[nf][2];
            ls[(r + 8) * 65 + e0 + 1] = acc[nf][3];
        }
    }
    __syncthreads();

    if (tid < BM) {
        const float NEG = __int_as_float(0xff800000);
        float m1 = NEG, m2 = NEG, m3 = NEG;
        int i1 = 0, i2 = 0;
        #pragma unroll
        for (int e = 0; e < NEXP; ++e) {
            float v = ls[tid * 65 + e] + biasArr[e];
            if (v > m1)      { m3 = m2; m2 = m1; i2 = i1; m1 = v; i1 = e; }
            else if (v > m2) { m3 = m2; m2 = v; i2 = e; }
            else if (v > m3) { m3 = v; }
        }
        float ssum = 0.0f;
        #pragma unroll
        for (int e = 0; e < NEXP; ++e)
            ssum += expf(ls[tid * 65 + e] + biasArr[e] - m1);

        const int tok = m0 + tid;
        out[(size_t)tok * 2 + 0] = (float)i1;
        out[(size_t)tok * 2 + 1] = (float)i2;
        out[(size_t)2 * NTOK + tok * 2 + 0] = 1.0f / ssum;
        out[(size_t)2 * NTOK + tok * 2 + 1] = expf(m2 - m1) / ssum;

        if ((m1 - m2) < TAU || (m2 - m3) < TAU) {
            int ix = atomicAdd(&g_count, 1);
            if (ix < NTOK) g_flags[ix] = tok;
        }
    }
}

// ---------- rescue: exact fp32 recompute for flagged tokens ----------
__global__ void rescue_kernel(const float* __restrict__ x,
                              const float* __restrict__ W,
                              const float* __restrict__ b,
                              float* __restrict__ out) {
    __shared__ float lg[NEXP];
    int cnt = g_count;
    if (cnt > NTOK) cnt = NTOK;
    const int e = threadIdx.x >> 2, q = threadIdx.x & 3;

    for (int i = blockIdx.x; i < cnt; i += gridDim.x) {
        const int tok = g_flags[i];
        const float* xr = x + (size_t)tok * DIM;
        float s = 0.0f;
        const int k0 = q * (DIM / 4);
        for (int k = k0; k < k0 + DIM / 4; ++k)
            s = fmaf(xr[k], W[(size_t)k * NEXP + e], s);
        s += __shfl_xor_sync(0xffffffffu, s, 1);
        s += __shfl_xor_sync(0xffffffffu, s, 2);
        if (q == 0) lg[e] = s + b[e];
        __syncthreads();

        if (threadIdx.x == 0) {
            const float NEG = __int_as_float(0xff800000);
            float m1 = NEG, m2 = NEG;
            int i1 = 0, i2 = 0;
            for (int ee = 0; ee < NEXP; ++ee) {
                float v = lg[ee];
                if (v > m1)      { m2 = m1; i2 = i1; m1 = v; i1 = ee; }
                else if (v > m2) { m2 = v; i2 = ee; }
            }
            float ssum = 0.0f;
            for (int ee = 0; ee < NEXP; ++ee) ssum += expf(lg[ee] - m1);
            out[(size_t)tok * 2 + 0] = (float)i1;
            out[(size_t)tok * 2 + 1] = (float)i2;
            out[(size_t)2 * NTOK + tok * 2 + 0] = 1.0f / ssum;
            out[(size_t)2 * NTOK + tok * 2 + 1] = expf(m2 - m1) / ssum;
        }
        __syncthreads();
    }
}

extern "C" void kernel_launch(void* const* d_in, const int* in_sizes, int n_in,
                              void* d_out, int out_size) {
    const float* x = (const float*)d_in[0];
    const float* W = (const float*)d_in[1];
    const float* b = (const float*)d_in[2];
    float* out = (float*)d_out;

    cudaFuncSetAttribute(router_mma_kernel,
                         cudaFuncAttributeMaxDynamicSharedMemorySize, SMEM_SZ);

    prep_w_kernel<<<DIM / 32, 256>>>(W);
    router_mma_kernel<<<NTOK / BM, 256, SMEM_SZ>>>(x, b, out);
    rescue_kernel<<<64, 256>>>(x, W, b, out);
}